// round 2
// baseline (speedup 1.0000x reference)
#include <cuda_runtime.h>

// 2D Haar DWT, fp32, x:[16,64,512,512] -> out:[4,16,64,256,256]
// Pure streaming: 1 GiB in + 1 GiB out. DRAM-bound (R1: 87.7% DRAM, 6.95 TB/s).
// R2: streaming cache hints (__ldcs/__stcs) + 8 output cols per thread
// (8 front-batched LDG.128 -> deeper MLP per warp).
//
//   ll = 0.5*(a+b+c+d)   lh = 0.5*(a+b-c-d)
//   hl = 0.5*(a-b+c-d)   hh = 0.5*(a-b-c+d)

static constexpr int W_IN  = 512;
static constexpr int H_IN  = 512;
static constexpr int W_OUT = 256;
static constexpr int H_OUT = 256;
static constexpr int PLANES = 16 * 64;                                  // 1024
static constexpr long long OUT_PLANE = (long long)W_OUT * H_OUT;        // 65536
static constexpr long long BAND_STRIDE = (long long)PLANES * OUT_PLANE; // 67,108,864

__device__ __forceinline__ float4 ldcs4(const float* p) {
    return __ldcs(reinterpret_cast<const float4*>(p));
}

__global__ __launch_bounds__(256) void haar_dwt_kernel(
    const float* __restrict__ x, float* __restrict__ out)
{
    unsigned idx = blockIdx.x * 256u + threadIdx.x;   // 0 .. 8,388,607
    unsigned tx = idx & 31u;          // 8-col group within row (32 groups * 8 = 256 cols)
    unsigned h  = (idx >> 5) & 255u;  // output row
    unsigned p  = idx >> 13;          // plane 0..1023

    // Input: rows 2h, 2h+1 of plane p, 16 consecutive floats starting at col 16*tx.
    const float* base = x + (size_t)p * (W_IN * H_IN) + (size_t)(2u * h) * W_IN + tx * 16u;

    // Front-batch all 8 loads (MLP=8).
    float4 r0[4], r1[4];
    r0[0] = ldcs4(base +  0);
    r0[1] = ldcs4(base +  4);
    r0[2] = ldcs4(base +  8);
    r0[3] = ldcs4(base + 12);
    r1[0] = ldcs4(base + W_IN +  0);
    r1[1] = ldcs4(base + W_IN +  4);
    r1[2] = ldcs4(base + W_IN +  8);
    r1[3] = ldcs4(base + W_IN + 12);

    float4 ll[2], lh[2], hl[2], hh[2];

    #pragma unroll
    for (int g = 0; g < 2; g++) {           // g: which output float4 (cols 4g..4g+3)
        float* llp = &ll[g].x; float* lhp = &lh[g].x;
        float* hlp = &hl[g].x; float* hhp = &hh[g].x;
        #pragma unroll
        for (int c = 0; c < 4; c++) {       // output col within group
            int v = g * 8 + c * 2;          // input col pair start (0..14)
            const float* t0 = &r0[v / 4].x;
            const float* t1 = &r1[v / 4].x;
            float a = t0[v % 4], b = t0[v % 4 + 1];
            float cc = t1[v % 4], d = t1[v % 4 + 1];
            float sT = a + b, dT = a - b;
            float sB = cc + d, dB = cc - d;
            llp[c] = 0.5f * (sT + sB);
            lhp[c] = 0.5f * (sT - sB);
            hlp[c] = 0.5f * (dT + dB);
            hhp[c] = 0.5f * (dT - dB);
        }
    }

    float* o = out + (size_t)p * OUT_PLANE + (size_t)h * W_OUT + tx * 8u;
    __stcs(reinterpret_cast<float4*>(o),                       ll[0]);
    __stcs(reinterpret_cast<float4*>(o + 4),                   ll[1]);
    __stcs(reinterpret_cast<float4*>(o + BAND_STRIDE),         lh[0]);
    __stcs(reinterpret_cast<float4*>(o + BAND_STRIDE + 4),     lh[1]);
    __stcs(reinterpret_cast<float4*>(o + 2 * BAND_STRIDE),     hl[0]);
    __stcs(reinterpret_cast<float4*>(o + 2 * BAND_STRIDE + 4), hl[1]);
    __stcs(reinterpret_cast<float4*>(o + 3 * BAND_STRIDE),     hh[0]);
    __stcs(reinterpret_cast<float4*>(o + 3 * BAND_STRIDE + 4), hh[1]);
}

extern "C" void kernel_launch(void* const* d_in, const int* in_sizes, int n_in,
                              void* d_out, int out_size) {
    const float* x = (const float*)d_in[0];
    float* out = (float*)d_out;
    // total threads = 1024 planes * 256 rows * 32 groups = 8,388,608
    unsigned total = (unsigned)PLANES * H_OUT * (W_OUT / 8);
    haar_dwt_kernel<<<total / 256, 256>>>(x, out);
}

// round 3
// speedup vs baseline: 1.0405x; 1.0405x over previous
#include <cuda_runtime.h>

// 2D Haar DWT, fp32, x:[16,64,512,512] -> out:[4,16,64,256,256]
// Pure streaming: 1 GiB in + 1 GiB out. DRAM-bound.
// R1 structure (4 output cols/thread, 32 regs, occ 76%, 6.95 TB/s) —
// R2's thread coarsening regressed (occ 49.5%, DRAM 81.6%), reverted.
// R3: single change vs R1 — __stcs (evict-first) on output stores only.
//
//   ll = 0.5*(a+b+c+d)   lh = 0.5*(a+b-c-d)
//   hl = 0.5*(a-b+c-d)   hh = 0.5*(a-b-c+d)

static constexpr int W_IN  = 512;
static constexpr int H_IN  = 512;
static constexpr int W_OUT = 256;
static constexpr int H_OUT = 256;
static constexpr int PLANES = 16 * 64;                                  // 1024
static constexpr long long OUT_PLANE = (long long)W_OUT * H_OUT;        // 65536
static constexpr long long BAND_STRIDE = (long long)PLANES * OUT_PLANE; // 67,108,864

__global__ __launch_bounds__(256) void haar_dwt_kernel(
    const float* __restrict__ x, float* __restrict__ out)
{
    unsigned idx = blockIdx.x * 256u + threadIdx.x;   // 0 .. 16,777,215
    unsigned tx = idx & 63u;          // 4-col group within row (64 groups * 4 = 256 cols)
    unsigned h  = (idx >> 6) & 255u;  // output row
    unsigned p  = idx >> 14;          // plane 0..1023

    // Input: row 2h and 2h+1 of plane p, 8 consecutive floats starting at col 8*tx.
    const float* base = x + (size_t)p * (W_IN * H_IN) + (size_t)(2u * h) * W_IN + tx * 8u;
    float4 r0a = *reinterpret_cast<const float4*>(base);
    float4 r0b = *reinterpret_cast<const float4*>(base + 4);
    float4 r1a = *reinterpret_cast<const float4*>(base + W_IN);
    float4 r1b = *reinterpret_cast<const float4*>(base + W_IN + 4);

    float4 ll, lh, hl, hh;

    {
        float sT = r0a.x + r0a.y, dT = r0a.x - r0a.y;
        float sB = r1a.x + r1a.y, dB = r1a.x - r1a.y;
        ll.x = 0.5f * (sT + sB); lh.x = 0.5f * (sT - sB);
        hl.x = 0.5f * (dT + dB); hh.x = 0.5f * (dT - dB);
    }
    {
        float sT = r0a.z + r0a.w, dT = r0a.z - r0a.w;
        float sB = r1a.z + r1a.w, dB = r1a.z - r1a.w;
        ll.y = 0.5f * (sT + sB); lh.y = 0.5f * (sT - sB);
        hl.y = 0.5f * (dT + dB); hh.y = 0.5f * (dT - dB);
    }
    {
        float sT = r0b.x + r0b.y, dT = r0b.x - r0b.y;
        float sB = r1b.x + r1b.y, dB = r1b.x - r1b.y;
        ll.z = 0.5f * (sT + sB); lh.z = 0.5f * (sT - sB);
        hl.z = 0.5f * (dT + dB); hh.z = 0.5f * (dT - dB);
    }
    {
        float sT = r0b.z + r0b.w, dT = r0b.z - r0b.w;
        float sB = r1b.z + r1b.w, dB = r1b.z - r1b.w;
        ll.w = 0.5f * (sT + sB); lh.w = 0.5f * (sT - sB);
        hl.w = 0.5f * (dT + dB); hh.w = 0.5f * (dT - dB);
    }

    float* o = out + (size_t)p * OUT_PLANE + (size_t)h * W_OUT + tx * 4u;
    __stcs(reinterpret_cast<float4*>(o),                   ll);
    __stcs(reinterpret_cast<float4*>(o + BAND_STRIDE),     lh);
    __stcs(reinterpret_cast<float4*>(o + 2 * BAND_STRIDE), hl);
    __stcs(reinterpret_cast<float4*>(o + 3 * BAND_STRIDE), hh);
}

extern "C" void kernel_launch(void* const* d_in, const int* in_sizes, int n_in,
                              void* d_out, int out_size) {
    const float* x = (const float*)d_in[0];
    float* out = (float*)d_out;
    // total threads = 1024 planes * 256 rows * 64 groups = 16,777,216
    unsigned total = (unsigned)PLANES * H_OUT * (W_OUT / 4);
    haar_dwt_kernel<<<total / 256, 256>>>(x, out);
}